// round 15
// baseline (speedup 1.0000x reference)
#include <cuda_runtime.h>

#define NC 4096
#define NA 2048
#define NB (NC + NA)          // 6144 bodies
#define TPB 128
#define IPT 2
#define ITILE (TPB * IPT)     // 256 i-bodies per block
#define ITILES (NB / ITILE)   // 24 i-tiles: 0..15 circle, 16..23 aabb
#define NCIT (NC / ITILE)     // 16
#define CHUNK 64              // j-chunk size
#define NCY (NC / CHUNK)      // 64 circle j-chunks
#define NAY (NA / CHUNK)      // 32 aabb j-chunks
#define NJY (NCY + NAY)       // 96 j-chunks
#define EPSF 1e-9f

// partial corrections: [NJY][NB] float2
__device__ float2 g_partial[NJY * NB];
__device__ int    g_cnt[ITILES] = {};

__device__ __forceinline__ float rsq_approx(float x) {
    float r;
    asm("rsqrt.approx.f32 %0, %1;" : "=f"(r) : "f"(x));
    return r;
}

__global__ void __launch_bounds__(TPB)
collide_kernel(const float* __restrict__ cpos, const float* __restrict__ crad,
               const float* __restrict__ apos, const float* __restrict__ ahalf,
               float* __restrict__ out)
{
    // one float4 per j-body: circle (−x, −y, 0.5*r, 0) ; aabb (−x, −y, hx, hy)
    __shared__ float4 sj[CHUNK];
    __shared__ int s_old;

    const int tid = threadIdx.x;
    const int jy  = blockIdx.x;                 // j-chunk (x-major mixes costs)
    const int bx  = blockIdx.y;                 // i-tile
    const int i0  = bx * ITILE + tid;           // first i-body
    const int i1  = i0 + TPB;                   // second i-body (same type)
    const bool i_is_circle = (bx < NCIT);
    const bool j_is_circle = (jy < NCY);
    const int j0 = j_is_circle ? (jy * CHUNK) : ((jy - NCY) * CHUNK);

    // stage CHUNK j-bodies (threads 0..63), positions negated
    if (tid < CHUNK) {
        if (j_is_circle) {
            float2 p = ((const float2*)cpos)[j0 + tid];
            sj[tid] = make_float4(-p.x, -p.y, 0.5f * crad[j0 + tid], 0.0f);
        } else {
            float2 p = ((const float2*)apos)[j0 + tid];
            float2 h = ((const float2*)ahalf)[j0 + tid];
            sj[tid] = make_float4(-p.x, -p.y, h.x, h.y);
        }
    }

    // hoisted i-state for both bodies
    float px0, py0, ra0, rb0, px1, py1, ra1, rb1;
    int ia0 = 0, ia1 = 0;
    if (i_is_circle) {
        float2 p0 = ((const float2*)cpos)[i0];
        float2 p1 = ((const float2*)cpos)[i1];
        px0 = p0.x; py0 = p0.y; ra0 = 0.5f * crad[i0]; rb0 = 0.0f;
        px1 = p1.x; py1 = p1.y; ra1 = 0.5f * crad[i1]; rb1 = 0.0f;
    } else {
        ia0 = i0 - NC; ia1 = i1 - NC;
        float2 p0 = ((const float2*)apos)[ia0];
        float2 p1 = ((const float2*)apos)[ia1];
        float2 h0 = ((const float2*)ahalf)[ia0];
        float2 h1 = ((const float2*)ahalf)[ia1];
        px0 = p0.x; py0 = p0.y; ra0 = h0.x; rb0 = h0.y;
        px1 = p1.x; py1 = p1.y; ra1 = h1.x; rb1 = h1.y;
    }
    const float nra0 = -ra0, nrb0 = -rb0, nra1 = -ra1, nrb1 = -rb1;

    __syncthreads();

    float cx0 = 0.0f, cy0 = 0.0f, cx1 = 0.0f, cy1 = 0.0f;

    if (i_is_circle) {
        if (j_is_circle) {
            // circle vs circle (EPS clamp => self-pair contributes exactly 0)
            #pragma unroll 8
            for (int k = 0; k < CHUNK; k++) {
                float4 b = sj[k];
                float dx0 = px0 + b.x, dy0 = py0 + b.y;
                float dx1 = px1 + b.x, dy1 = py1 + b.y;
                float d20 = fmaxf(fmaf(dx0, dx0, dy0 * dy0), EPSF);
                float d21 = fmaxf(fmaf(dx1, dx1, dy1 * dy1), EPSF);
                float inv0 = rsq_approx(d20);
                float inv1 = rsq_approx(d21);
                float s0 = fmaxf(fmaf(ra0 + b.z, inv0, -0.5f), 0.0f);
                float s1 = fmaxf(fmaf(ra1 + b.z, inv1, -0.5f), 0.0f);
                cx0 = fmaf(s0, dx0, cx0);  cy0 = fmaf(s0, dy0, cy0);
                cx1 = fmaf(s1, dx1, cx1);  cy1 = fmaf(s1, dy1, cy1);
            }
        } else {
            // circle vs aabb (push on circle)
            #pragma unroll 8
            for (int k = 0; k < CHUNK; k++) {
                float4 b = sj[k];
                float rx0 = px0 + b.x, ry0 = py0 + b.y;
                float rx1 = px1 + b.x, ry1 = py1 + b.y;
                float dx0 = rx0 - fminf(fmaxf(rx0, -b.z), b.z);
                float dy0 = ry0 - fminf(fmaxf(ry0, -b.w), b.w);
                float dx1 = rx1 - fminf(fmaxf(rx1, -b.z), b.z);
                float dy1 = ry1 - fminf(fmaxf(ry1, -b.w), b.w);
                float d20 = fmaxf(fmaf(dx0, dx0, dy0 * dy0), EPSF);
                float d21 = fmaxf(fmaf(dx1, dx1, dy1 * dy1), EPSF);
                float inv0 = rsq_approx(d20);
                float inv1 = rsq_approx(d21);
                float s0 = fmaxf(fmaf(ra0, inv0, -0.5f), 0.0f);   // ra = 0.5*ri
                float s1 = fmaxf(fmaf(ra1, inv1, -0.5f), 0.0f);
                cx0 = fmaf(s0, dx0, cx0);  cy0 = fmaf(s0, dy0, cy0);
                cx1 = fmaf(s1, dx1, cx1);  cy1 = fmaf(s1, dy1, cy1);
            }
        }
    } else {
        if (j_is_circle) {
            // aabb vs circle: rel' = ai - cj = -rel => box push = +s*diff'
            #pragma unroll 8
            for (int k = 0; k < CHUNK; k++) {
                float4 b = sj[k];
                float rx0 = px0 + b.x, ry0 = py0 + b.y;
                float rx1 = px1 + b.x, ry1 = py1 + b.y;
                float dx0 = rx0 - fminf(fmaxf(rx0, nra0), ra0);
                float dy0 = ry0 - fminf(fmaxf(ry0, nrb0), rb0);
                float dx1 = rx1 - fminf(fmaxf(rx1, nra1), ra1);
                float dy1 = ry1 - fminf(fmaxf(ry1, nrb1), rb1);
                float d20 = fmaxf(fmaf(dx0, dx0, dy0 * dy0), EPSF);
                float d21 = fmaxf(fmaf(dx1, dx1, dy1 * dy1), EPSF);
                float inv0 = rsq_approx(d20);
                float inv1 = rsq_approx(d21);
                float s0 = fmaxf(fmaf(b.z, inv0, -0.5f), 0.0f);   // b.z = 0.5*rj
                float s1 = fmaxf(fmaf(b.z, inv1, -0.5f), 0.0f);
                cx0 = fmaf(s0, dx0, cx0);  cy0 = fmaf(s0, dy0, cy0);
                cx1 = fmaf(s1, dx1, cx1);  cy1 = fmaf(s1, dy1, cy1);
            }
        } else {
            // aabb vs aabb — guard self-pair only when the chunk lies in this tile
            const int tile_a0 = (bx - NCIT) * ITILE;       // aabb-local tile start
            const int j0a = (jy - NCY) * CHUNK;            // aabb-local chunk start
            if (j0a >= tile_a0 && j0a < tile_a0 + ITILE) {
                #pragma unroll 8
                for (int k = 0; k < CHUNK; k++) {
                    float4 b = sj[k];
                    int j = j0 + k;
                    float dax0 = px0 + b.x, day0 = py0 + b.y;
                    float dax1 = px1 + b.x, day1 = py1 + b.y;
                    float ovx0 = (ra0 + b.z) - fabsf(dax0);
                    float ovy0 = (rb0 + b.w) - fabsf(day0);
                    float ovx1 = (ra1 + b.z) - fabsf(dax1);
                    float ovy1 = (rb1 + b.w) - fabsf(day1);
                    bool h0 = (ovx0 > 0.0f) && (ovy0 > 0.0f) && (ia0 != j);
                    bool h1 = (ovx1 > 0.0f) && (ovy1 > 0.0f) && (ia1 != j);
                    bool u0 = (ovx0 <= ovy0);
                    bool u1 = (ovx1 <= ovy1);
                    cx0 += (h0 && u0)  ? copysignf(0.5f * ovx0, dax0) : 0.0f;
                    cy0 += (h0 && !u0) ? copysignf(0.5f * ovy0, day0) : 0.0f;
                    cx1 += (h1 && u1)  ? copysignf(0.5f * ovx1, dax1) : 0.0f;
                    cy1 += (h1 && !u1) ? copysignf(0.5f * ovy1, day1) : 0.0f;
                }
            } else {
                #pragma unroll 8
                for (int k = 0; k < CHUNK; k++) {
                    float4 b = sj[k];
                    float dax0 = px0 + b.x, day0 = py0 + b.y;
                    float dax1 = px1 + b.x, day1 = py1 + b.y;
                    float ovx0 = (ra0 + b.z) - fabsf(dax0);
                    float ovy0 = (rb0 + b.w) - fabsf(day0);
                    float ovx1 = (ra1 + b.z) - fabsf(dax1);
                    float ovy1 = (rb1 + b.w) - fabsf(day1);
                    bool h0 = (ovx0 > 0.0f) && (ovy0 > 0.0f);
                    bool h1 = (ovx1 > 0.0f) && (ovy1 > 0.0f);
                    bool u0 = (ovx0 <= ovy0);
                    bool u1 = (ovx1 <= ovy1);
                    cx0 += (h0 && u0)  ? copysignf(0.5f * ovx0, dax0) : 0.0f;
                    cy0 += (h0 && !u0) ? copysignf(0.5f * ovy0, day0) : 0.0f;
                    cx1 += (h1 && u1)  ? copysignf(0.5f * ovx1, dax1) : 0.0f;
                    cy1 += (h1 && !u1) ? copysignf(0.5f * ovy1, day1) : 0.0f;
                }
            }
        }
    }

    g_partial[(size_t)jy * NB + i0] = make_float2(cx0, cy0);
    g_partial[(size_t)jy * NB + i1] = make_float2(cx1, cy1);

    // ---- last-arriving block of this i-tile folds all partials (fixed order) ----
    __threadfence();                       // release partial writes
    if (tid == 0) s_old = atomicAdd(&g_cnt[bx], 1);
    __syncthreads();
    if (s_old == NJY - 1) {
        __threadfence();                   // see all partials
        #pragma unroll
        for (int v = 0; v < IPT; v++) {
            const int i = (v == 0) ? i0 : i1;
            float2 base = i_is_circle ? ((const float2*)cpos)[i]
                                      : ((const float2*)apos)[i - NC];
            float sx = base.x, sy = base.y;
            #pragma unroll 8
            for (int y = 0; y < NJY; y++) {    // fixed order => deterministic
                float2 p = g_partial[(size_t)y * NB + i];
                sx += p.x; sy += p.y;
            }
            ((float2*)out)[i] = make_float2(sx, sy);
        }
        if (tid == 0) g_cnt[bx] = 0;       // reset for next graph replay
    }
}

extern "C" void kernel_launch(void* const* d_in, const int* in_sizes, int n_in,
                              void* d_out, int out_size)
{
    const float* cpos  = (const float*)d_in[0];   // [4096,2]
    const float* crad  = (const float*)d_in[1];   // [4096]
    const float* apos  = (const float*)d_in[2];   // [2048,2]
    const float* ahalf = (const float*)d_in[3];   // [2048,2]
    float* out = (float*)d_out;                   // [6144,2]

    dim3 grid(NJY, ITILES);
    collide_kernel<<<grid, TPB>>>(cpos, crad, apos, ahalf, out);
}